// round 13
// baseline (speedup 1.0000x reference)
#include <cuda_runtime.h>
#include <math.h>

#define B_      16
#define H_      16
#define D_      128
#define MAXS    2048
#define NSPLIT  8
#define NWARP   8
#define NTHREAD 256
#define CHUNKMAX 256    // ceil(2047/8) = 256
#define SCALE   0.08838834764831845f

// Split-KV partial scratch (allocation-free: __device__ globals)
__device__ float g_po[B_ * H_ * NSPLIT * D_];
__device__ float g_pm[B_ * H_ * NSPLIT];
__device__ float g_pl[B_ * H_ * NSPLIT];
__device__ unsigned int g_cnt[B_ * H_];   // zero-init; reset by last CTA each call

__global__ __launch_bounds__(NTHREAD) void paged_attn_fused(
    const float* __restrict__ Q,
    const float* __restrict__ K,
    const float* __restrict__ V,
    const float* __restrict__ Kc,           // [flat_slot,H,D]
    const float* __restrict__ Vc,
    const float* __restrict__ cosT,         // [MAXS,1,D]
    const float* __restrict__ sinT,
    const float* __restrict__ mask,         // [B,MAXS]
    const int*   __restrict__ cache_length, // [B]
    const int*   __restrict__ fetch_slots,  // [B,128]
    float*       __restrict__ out)          // [B,H,D]
{
    const int split = blockIdx.x;
    const int h     = blockIdx.y;
    const int b     = blockIdx.z;
    const int tid   = threadIdx.x;
    const int w     = tid >> 5;
    const int lane  = tid & 31;

    const int newpos = cache_length[b];
    const int L      = newpos + 1;
    const int bh     = b * H_ + h;
    const int pbase  = bh * NSPLIT;

    // Dynamic per-batch chunking: all 8 splits carry (nearly) equal length.
    const int chunk = (L + NSPLIT - 1) / NSPLIT;
    const int s0    = split * chunk;
    const int nact  = min(NSPLIT, (L + chunk - 1) / chunk);

    __shared__ __align__(16) float sh_q[D_];
    __shared__ __align__(16) float sh_k[D_];
    __shared__ __align__(16) float sh_v[D_];
    __shared__ __align__(16) float sh_acc[NWARP][D_];
    __shared__ __align__(16) float sh_mask[CHUNKMAX];
    __shared__ float sh_m[NWARP];
    __shared__ float sh_l[NWARP];
    __shared__ int   sh_fs[CHUNKMAX / 16 + 2];
    __shared__ unsigned int sh_rank;

    const bool active = (s0 < L);

    if (active) {
        const int s1  = min(s0 + chunk, L);
        const int len = s1 - s0;
        const int f0  = s0 >> 4;
        const int nfs = ((s1 - 1) >> 4) - f0 + 1;

        // Prologue across all 256 threads: 0-127 RoPE Q/K, 128-255 load V.
        if (tid < D_) {
            const float c  = cosT[(size_t)newpos * D_ + tid];
            const float sn = sinT[(size_t)newpos * D_ + tid];
            const float* qrow = Q + (size_t)bh * D_;
            const float* krow = K + (size_t)bh * D_;
            const float qrot = (tid < 64) ? -qrow[tid + 64] : qrow[tid - 64];
            const float krot = (tid < 64) ? -krow[tid + 64] : krow[tid - 64];
            sh_q[tid] = qrow[tid] * c + qrot * sn;
            sh_k[tid] = krow[tid] * c + krot * sn;
        } else {
            const int d = tid - D_;
            sh_v[d] = V[(size_t)bh * D_ + d];
        }
        for (int i = tid; i < len; i += NTHREAD)
            sh_mask[i] = mask[(size_t)b * MAXS + s0 + i];
        if (tid < nfs)
            sh_fs[tid] = fetch_slots[b * 128 + f0 + tid];
        __syncthreads();

        const float4 q4 = reinterpret_cast<const float4*>(sh_q)[lane];

        float  m = -1e30f, l = 0.f;
        float4 acc = make_float4(0.f, 0.f, 0.f, 0.f);

        // Hot loop: 2-way unrolled, fused 2-element online-softmax update.
        const int send = min(s1, newpos);
        int s = s0 + w;
        for (; s + NWARP < send; s += 2 * NWARP) {
            const int sA = s, sB = s + NWARP;
            const int slotA = sh_fs[(sA >> 4) - f0] * 16 + (sA & 15);
            const int slotB = sh_fs[(sB >> 4) - f0] * 16 + (sB & 15);
            const float4 k4a = __ldcs(reinterpret_cast<const float4*>(Kc + ((size_t)slotA * H_ + h) * D_) + lane);
            const float4 v4a = __ldcs(reinterpret_cast<const float4*>(Vc + ((size_t)slotA * H_ + h) * D_) + lane);
            const float4 k4b = __ldcs(reinterpret_cast<const float4*>(Kc + ((size_t)slotB * H_ + h) * D_) + lane);
            const float4 v4b = __ldcs(reinterpret_cast<const float4*>(Vc + ((size_t)slotB * H_ + h) * D_) + lane);

            float dotA = q4.x * k4a.x + q4.y * k4a.y + q4.z * k4a.z + q4.w * k4a.w;
            float dotB = q4.x * k4b.x + q4.y * k4b.y + q4.z * k4b.z + q4.w * k4b.w;
            #pragma unroll
            for (int o = 16; o; o >>= 1) {
                dotA += __shfl_xor_sync(0xffffffffu, dotA, o);
                dotB += __shfl_xor_sync(0xffffffffu, dotB, o);
            }
            const float scA = dotA * SCALE + sh_mask[sA - s0];
            const float scB = dotB * SCALE + sh_mask[sB - s0];

            const float mn   = fmaxf(m, fmaxf(scA, scB));
            const float corr = __expf(m - mn);
            const float pA   = __expf(scA - mn);
            const float pB   = __expf(scB - mn);
            l = l * corr + pA + pB;
            acc.x = acc.x * corr + pA * v4a.x + pB * v4b.x;
            acc.y = acc.y * corr + pA * v4a.y + pB * v4b.y;
            acc.z = acc.z * corr + pA * v4a.z + pB * v4b.z;
            acc.w = acc.w * corr + pA * v4a.w + pB * v4b.w;
            m = mn;
        }
        if (s < send) {
            const int slot = sh_fs[(s >> 4) - f0] * 16 + (s & 15);
            const float4 k4 = __ldcs(reinterpret_cast<const float4*>(Kc + ((size_t)slot * H_ + h) * D_) + lane);
            const float4 v4 = __ldcs(reinterpret_cast<const float4*>(Vc + ((size_t)slot * H_ + h) * D_) + lane);
            float dot = q4.x * k4.x + q4.y * k4.y + q4.z * k4.z + q4.w * k4.w;
            #pragma unroll
            for (int o = 16; o; o >>= 1) dot += __shfl_xor_sync(0xffffffffu, dot, o);
            const float sc = dot * SCALE + sh_mask[s - s0];
            const float mn   = fmaxf(m, sc);
            const float corr = __expf(m - mn);
            const float p    = __expf(sc - mn);
            l = l * corr + p;
            acc.x = acc.x * corr + p * v4.x;
            acc.y = acc.y * corr + p * v4.y;
            acc.z = acc.z * corr + p * v4.z;
            acc.w = acc.w * corr + p * v4.w;
            m = mn;
        }

        // New token: warp 0 of the owning split.
        if (w == 0 && newpos >= s0 && newpos < s1) {
            const float4 k4 = reinterpret_cast<const float4*>(sh_k)[lane];
            const float4 v4 = reinterpret_cast<const float4*>(sh_v)[lane];
            float dot = q4.x * k4.x + q4.y * k4.y + q4.z * k4.z + q4.w * k4.w;
            #pragma unroll
            for (int o = 16; o; o >>= 1) dot += __shfl_xor_sync(0xffffffffu, dot, o);
            const float sc = dot * SCALE + sh_mask[newpos - s0];
            const float mn   = fmaxf(m, sc);
            const float corr = __expf(m - mn);
            const float p    = __expf(sc - mn);
            l = l * corr + p;
            acc.x = acc.x * corr + p * v4.x;
            acc.y = acc.y * corr + p * v4.y;
            acc.z = acc.z * corr + p * v4.z;
            acc.w = acc.w * corr + p * v4.w;
            m = mn;
        }

        // Merge 8 warps, write split partial.
        if (lane == 0) { sh_m[w] = m; sh_l[w] = l; }
        reinterpret_cast<float4*>(sh_acc[w])[lane] = acc;
        __syncthreads();

        if (tid < D_) {
            float M = sh_m[0];
            #pragma unroll
            for (int i = 1; i < NWARP; i++) M = fmaxf(M, sh_m[i]);
            float od = 0.f, lt = 0.f;
            #pragma unroll
            for (int i = 0; i < NWARP; i++) {
                const float e = __expf(sh_m[i] - M);
                od += e * sh_acc[i][tid];
                lt += e * sh_l[i];
            }
            g_po[(pbase + split) * D_ + tid] = od;
            if (tid == 0) { g_pm[pbase + split] = M; g_pl[pbase + split] = lt; }
        }
        __threadfence();
    }

    // Arrival + last-CTA combine.
    if (tid == 0) sh_rank = atomicAdd(&g_cnt[bh], 1u);
    __syncthreads();

    if (sh_rank == NSPLIT - 1) {
        if (tid < D_) {
            float pm[NSPLIT];
            float M = -1e30f;
            #pragma unroll
            for (int i = 0; i < NSPLIT; i++) {
                pm[i] = (i < nact) ? g_pm[pbase + i] : -1e30f;
                M = fmaxf(M, pm[i]);
            }
            float denom = 0.f, od = 0.f;
            for (int i = 0; i < nact; i++) {
                const float e = __expf(pm[i] - M);
                denom += e * g_pl[pbase + i];
                od    += e * g_po[(pbase + i) * D_ + tid];
            }
            out[(size_t)bh * D_ + tid] = od / denom;
        }
        if (tid == 0) g_cnt[bh] = 0;   // reset for next graph replay
    }
}

// Inputs (metadata order):
//  0 Q  1 K  2 V  3 Kcache  4 Vcache  5 cos  6 sin  7 mask
//  8 input_length  9 cache_length  10 save_slots  11 fetch_slots  12 max_s
extern "C" void kernel_launch(void* const* d_in, const int* in_sizes, int n_in,
                              void* d_out, int out_size)
{
    const float* Q    = (const float*)d_in[0];
    const float* K    = (const float*)d_in[1];
    const float* V    = (const float*)d_in[2];
    const float* Kc   = (const float*)d_in[3];
    const float* Vc   = (const float*)d_in[4];
    const float* cosT = (const float*)d_in[5];
    const float* sinT = (const float*)d_in[6];
    const float* mask = (const float*)d_in[7];
    const int*   clen = (const int*)d_in[9];
    const int*   fsl  = (const int*)d_in[11];
    float* out = (float*)d_out;

    dim3 grid(NSPLIT, H_, B_);   // proven-best ordering (R4)
    paged_attn_fused<<<grid, NTHREAD>>>(Q, K, V, Kc, Vc, cosT, sinT, mask, clen, fsl, out);
}

// round 14
// speedup vs baseline: 1.1181x; 1.1181x over previous
#include <cuda_runtime.h>
#include <math.h>

#define B_      16
#define H_      16
#define D_      128
#define MAXS    2048
#define NSPLIT  8
#define NWARP   8
#define NTHREAD 256
#define CHUNKMAX 256    // ceil(2047/8) = 256

// Split-KV partial scratch (allocation-free: __device__ globals)
__device__ float g_po[B_ * H_ * NSPLIT * D_];
__device__ float g_pm[B_ * H_ * NSPLIT];
__device__ float g_pl[B_ * H_ * NSPLIT];
__device__ unsigned int g_cnt[B_ * H_];   // zero-init; reset by last CTA each call

__global__ __launch_bounds__(NTHREAD) void paged_attn_fused(
    const float* __restrict__ Q,
    const float* __restrict__ K,
    const float* __restrict__ V,
    const float* __restrict__ Kc,           // [flat_slot,H,D]
    const float* __restrict__ Vc,
    const float* __restrict__ cosT,         // [MAXS,1,D]
    const float* __restrict__ sinT,
    const float* __restrict__ mask,         // [B,MAXS]
    const int*   __restrict__ cache_length, // [B]
    const int*   __restrict__ fetch_slots,  // [B,128]
    float*       __restrict__ out)          // [B,H,D]
{
    const int split = blockIdx.x;
    const int h     = blockIdx.y;
    const int b     = blockIdx.z;
    const int tid   = threadIdx.x;
    const int w     = tid >> 5;
    const int lane  = tid & 31;

    const int newpos = cache_length[b];
    const int L      = newpos + 1;
    const int bh     = b * H_ + h;
    const int pbase  = bh * NSPLIT;

    // Dynamic per-batch chunking: all 8 splits carry (nearly) equal length.
    const int chunk = (L + NSPLIT - 1) / NSPLIT;
    const int s0    = split * chunk;
    const int nact  = min(NSPLIT, (L + chunk - 1) / chunk);

    // All float4-accessed shared arrays explicitly 16B-aligned; oddly sized
    // arrays (sh_fs, scalars) placed after them.
    __shared__ __align__(16) float sh_q[D_];
    __shared__ __align__(16) float sh_k[D_];
    __shared__ __align__(16) float sh_v[D_];
    __shared__ __align__(16) float sh_acc[NWARP][D_];
    __shared__ __align__(16) float sh_mask[CHUNKMAX];
    __shared__ float sh_m[NWARP];
    __shared__ float sh_l[NWARP];
    __shared__ int   sh_fs[CHUNKMAX / 16 + 2];
    __shared__ unsigned int sh_rank;

    const bool active = (s0 < L);

    if (active) {
        const int s1  = min(s0 + chunk, L);
        const int len = s1 - s0;
        const int f0  = s0 >> 4;                       // first block-table entry
        const int nfs = ((s1 - 1) >> 4) - f0 + 1;      // #entries this chunk touches

        // Prologue: RoPE'd Q/K + new-token V, mask chunk, fetch-slot chunk.
        if (tid < D_) {
            const float c  = cosT[(size_t)newpos * D_ + tid];
            const float sn = sinT[(size_t)newpos * D_ + tid];
            const float* qrow = Q + (size_t)bh * D_;
            const float* krow = K + (size_t)bh * D_;
            const float qrot = (tid < 64) ? -qrow[tid + 64] : qrow[tid - 64];
            const float krot = (tid < 64) ? -krow[tid + 64] : krow[tid - 64];
            sh_q[tid] = qrow[tid] * c + qrot * sn;
            sh_k[tid] = krow[tid] * c + krot * sn;
            sh_v[tid] = V[(size_t)bh * D_ + tid];
        }
        for (int i = tid; i < len; i += NTHREAD)
            sh_mask[i] = mask[(size_t)b * MAXS + s0 + i];
        if (tid < nfs)
            sh_fs[tid] = fetch_slots[b * 128 + f0 + tid];
        __syncthreads();

        const float4 q4 = reinterpret_cast<const float4*>(sh_q)[lane];
        const float scale = 0.08838834764831845f;   // 1/sqrt(128)

        float  m = -1e30f, l = 0.f;
        float4 acc = make_float4(0.f, 0.f, 0.f, 0.f);

        // Hot loop: cached positions strictly below newpos, 2-way unrolled with
        // a fused 2-element online-softmax update (1 corr exp instead of 2).
        const int send = min(s1, newpos);
        int s = s0 + w;
        for (; s + NWARP < send; s += 2 * NWARP) {
            const int sA = s, sB = s + NWARP;
            const int slotA = sh_fs[(sA >> 4) - f0] * 16 + (sA & 15);
            const int slotB = sh_fs[(sB >> 4) - f0] * 16 + (sB & 15);
            const float4 k4a = __ldcs(reinterpret_cast<const float4*>(Kc + ((size_t)slotA * H_ + h) * D_) + lane);
            const float4 v4a = __ldcs(reinterpret_cast<const float4*>(Vc + ((size_t)slotA * H_ + h) * D_) + lane);
            const float4 k4b = __ldcs(reinterpret_cast<const float4*>(Kc + ((size_t)slotB * H_ + h) * D_) + lane);
            const float4 v4b = __ldcs(reinterpret_cast<const float4*>(Vc + ((size_t)slotB * H_ + h) * D_) + lane);

            float dotA = q4.x * k4a.x + q4.y * k4a.y + q4.z * k4a.z + q4.w * k4a.w;
            float dotB = q4.x * k4b.x + q4.y * k4b.y + q4.z * k4b.z + q4.w * k4b.w;
            #pragma unroll
            for (int o = 16; o; o >>= 1) {
                dotA += __shfl_xor_sync(0xffffffffu, dotA, o);
                dotB += __shfl_xor_sync(0xffffffffu, dotB, o);
            }
            const float scA = dotA * scale + sh_mask[sA - s0];
            const float scB = dotB * scale + sh_mask[sB - s0];

            const float mn   = fmaxf(m, fmaxf(scA, scB));
            const float corr = __expf(m - mn);
            const float pA   = __expf(scA - mn);
            const float pB   = __expf(scB - mn);
            l = l * corr + pA + pB;
            acc.x = acc.x * corr + pA * v4a.x + pB * v4b.x;
            acc.y = acc.y * corr + pA * v4a.y + pB * v4b.y;
            acc.z = acc.z * corr + pA * v4a.z + pB * v4b.z;
            acc.w = acc.w * corr + pA * v4a.w + pB * v4b.w;
            m = mn;
        }
        if (s < send) {
            const int slot = sh_fs[(s >> 4) - f0] * 16 + (s & 15);
            const float4 k4 = __ldcs(reinterpret_cast<const float4*>(Kc + ((size_t)slot * H_ + h) * D_) + lane);
            const float4 v4 = __ldcs(reinterpret_cast<const float4*>(Vc + ((size_t)slot * H_ + h) * D_) + lane);
            float dot = q4.x * k4.x + q4.y * k4.y + q4.z * k4.z + q4.w * k4.w;
            #pragma unroll
            for (int o = 16; o; o >>= 1) dot += __shfl_xor_sync(0xffffffffu, dot, o);
            const float sc = dot * scale + sh_mask[s - s0];
            const float mn   = fmaxf(m, sc);
            const float corr = __expf(m - mn);
            const float p    = __expf(sc - mn);
            l = l * corr + p;
            acc.x = acc.x * corr + p * v4.x;
            acc.y = acc.y * corr + p * v4.y;
            acc.z = acc.z * corr + p * v4.z;
            acc.w = acc.w * corr + p * v4.w;
            m = mn;
        }

        // New token (position == cache_length[b]): warp 0 of the owning split.
        if (w == 0 && newpos >= s0 && newpos < s1) {
            const float4 k4 = reinterpret_cast<const float4*>(sh_k)[lane];
            const float4 v4 = reinterpret_cast<const float4*>(sh_v)[lane];
            float dot = q4.x * k4.x + q4.y * k4.y + q4.z * k4.z + q4.w * k4.w;
            #pragma unroll
            for (int o = 16; o; o >>= 1) dot += __shfl_xor_sync(0xffffffffu, dot, o);
            const float sc = dot * scale + sh_mask[newpos - s0];
            const float mn   = fmaxf(m, sc);
            const float corr = __expf(m - mn);
            const float p    = __expf(sc - mn);
            l = l * corr + p;
            acc.x = acc.x * corr + p * v4.x;
            acc.y = acc.y * corr + p * v4.y;
            acc.z = acc.z * corr + p * v4.z;
            acc.w = acc.w * corr + p * v4.w;
            m = mn;
        }

        // Merge 8 warps in shared, write this split's partial.
        if (lane == 0) { sh_m[w] = m; sh_l[w] = l; }
        reinterpret_cast<float4*>(sh_acc[w])[lane] = acc;
        __syncthreads();

        if (tid < D_) {
            float M = sh_m[0];
            #pragma unroll
            for (int i = 1; i < NWARP; i++) M = fmaxf(M, sh_m[i]);
            float od = 0.f, lt = 0.f;
            #pragma unroll
            for (int i = 0; i < NWARP; i++) {
                const float e = __expf(sh_m[i] - M);
                od += e * sh_acc[i][tid];
                lt += e * sh_l[i];
            }
            g_po[(pbase + split) * D_ + tid] = od;
            if (tid == 0) { g_pm[pbase + split] = M; g_pl[pbase + split] = lt; }
        }
        __threadfence();
    }

    // Arrival + last-CTA combine.
    if (tid == 0) sh_rank = atomicAdd(&g_cnt[bh], 1u);
    __syncthreads();

    if (sh_rank == NSPLIT - 1) {
        if (tid < D_) {
            float M = -1e30f;
            for (int i = 0; i < nact; i++) M = fmaxf(M, g_pm[pbase + i]);
            float denom = 0.f, od = 0.f;
            for (int i = 0; i < nact; i++) {
                const float e = __expf(g_pm[pbase + i] - M);
                denom += e * g_pl[pbase + i];
                od    += e * g_po[(pbase + i) * D_ + tid];
            }
            out[(size_t)bh * D_ + tid] = od / denom;
        }
        if (tid == 0) g_cnt[bh] = 0;   // reset for next graph replay
    }
}

// Inputs (metadata order):
//  0 Q  1 K  2 V  3 Kcache  4 Vcache  5 cos  6 sin  7 mask
//  8 input_length  9 cache_length  10 save_slots  11 fetch_slots  12 max_s
extern "C" void kernel_launch(void* const* d_in, const int* in_sizes, int n_in,
                              void* d_out, int out_size)
{
    const float* Q    = (const float*)d_in[0];
    const float* K    = (const float*)d_in[1];
    const float* V    = (const float*)d_in[2];
    const float* Kc   = (const float*)d_in[3];
    const float* Vc   = (const float*)d_in[4];
    const float* cosT = (const float*)d_in[5];
    const float* sinT = (const float*)d_in[6];
    const float* mask = (const float*)d_in[7];
    const int*   clen = (const int*)d_in[9];
    const int*   fsl  = (const int*)d_in[11];
    float* out = (float*)d_out;

    dim3 grid(NSPLIT, H_, B_);
    paged_attn_fused<<<grid, NTHREAD>>>(Q, K, V, Kc, Vc, cosT, sinT, mask, clen, fsl, out);
}

// round 15
// speedup vs baseline: 1.1246x; 1.0058x over previous
#include <cuda_runtime.h>
#include <math.h>

#define B_      16
#define H_      16
#define D_      128
#define MAXS    2048
#define NSPLIT  8
#define NWARP   8
#define NTHREAD 256
#define CHUNKMAX 256    // ceil(2047/8) = 256

// Split-KV partial scratch (allocation-free: __device__ globals)
__device__ float g_po[B_ * H_ * NSPLIT * D_];
__device__ float g_pm[B_ * H_ * NSPLIT];
__device__ float g_pl[B_ * H_ * NSPLIT];
__device__ unsigned int g_cnt[B_ * H_];   // zero-init; reset by last CTA each call

__global__ __launch_bounds__(NTHREAD) void paged_attn_fused(
    const float* __restrict__ Q,
    const float* __restrict__ K,
    const float* __restrict__ V,
    const float* __restrict__ Kc,           // [flat_slot,H,D]
    const float* __restrict__ Vc,
    const float* __restrict__ cosT,         // [MAXS,1,D]
    const float* __restrict__ sinT,
    const float* __restrict__ mask,         // [B,MAXS]
    const int*   __restrict__ cache_length, // [B]
    const int*   __restrict__ fetch_slots,  // [B,128]
    float*       __restrict__ out)          // [B,H,D]
{
    const int split = blockIdx.x;
    const int h     = blockIdx.y;
    const int b     = blockIdx.z;
    const int tid   = threadIdx.x;
    const int w     = tid >> 5;
    const int lane  = tid & 31;

    const int newpos = cache_length[b];
    const int L      = newpos + 1;
    const int bh     = b * H_ + h;
    const int pbase  = bh * NSPLIT;

    // Dynamic per-batch chunking: all 8 splits carry (nearly) equal length.
    const int chunk = (L + NSPLIT - 1) / NSPLIT;
    const int s0    = split * chunk;
    const int nact  = min(NSPLIT, (L + chunk - 1) / chunk);

    // All float4-accessed shared arrays explicitly 16B-aligned; oddly sized
    // arrays (sh_fs, scalars) placed after them.
    __shared__ __align__(16) float sh_q[D_];
    __shared__ __align__(16) float sh_k[D_];
    __shared__ __align__(16) float sh_v[D_];
    __shared__ __align__(16) float sh_acc[NWARP][D_];
    __shared__ __align__(16) float sh_mask[CHUNKMAX];
    __shared__ float sh_m[NWARP];
    __shared__ float sh_l[NWARP];
    __shared__ int   sh_fs[CHUNKMAX / 16 + 2];
    __shared__ unsigned int sh_rank;

    const bool active = (s0 < L);

    if (active) {
        const int s1  = min(s0 + chunk, L);
        const int len = s1 - s0;
        const int f0  = s0 >> 4;                       // first block-table entry
        const int nfs = ((s1 - 1) >> 4) - f0 + 1;      // #entries this chunk touches

        // Prologue: RoPE'd Q/K + new-token V, mask chunk, fetch-slot chunk.
        if (tid < D_) {
            const float c  = cosT[(size_t)newpos * D_ + tid];
            const float sn = sinT[(size_t)newpos * D_ + tid];
            const float* qrow = Q + (size_t)bh * D_;
            const float* krow = K + (size_t)bh * D_;
            const float qrot = (tid < 64) ? -qrow[tid + 64] : qrow[tid - 64];
            const float krot = (tid < 64) ? -krow[tid + 64] : krow[tid - 64];
            sh_q[tid] = qrow[tid] * c + qrot * sn;
            sh_k[tid] = krow[tid] * c + krot * sn;
            sh_v[tid] = V[(size_t)bh * D_ + tid];
        }
        for (int i = tid; i < len; i += NTHREAD)
            sh_mask[i] = mask[(size_t)b * MAXS + s0 + i];
        if (tid < nfs)
            sh_fs[tid] = fetch_slots[b * 128 + f0 + tid];
        __syncthreads();

        const float4 q4 = reinterpret_cast<const float4*>(sh_q)[lane];
        const float scale = 0.08838834764831845f;   // 1/sqrt(128)

        float  m = -1e30f, l = 0.f;
        float4 acc = make_float4(0.f, 0.f, 0.f, 0.f);

        // Hot loop: cached positions strictly below newpos, 2-way unrolled with
        // a fused 2-element online-softmax update (1 corr exp instead of 2).
        const int send = min(s1, newpos);
        int s = s0 + w;
        for (; s + NWARP < send; s += 2 * NWARP) {
            const int sA = s, sB = s + NWARP;
            const int slotA = sh_fs[(sA >> 4) - f0] * 16 + (sA & 15);
            const int slotB = sh_fs[(sB >> 4) - f0] * 16 + (sB & 15);
            const float4 k4a = __ldcs(reinterpret_cast<const float4*>(Kc + ((size_t)slotA * H_ + h) * D_) + lane);
            const float4 v4a = __ldcs(reinterpret_cast<const float4*>(Vc + ((size_t)slotA * H_ + h) * D_) + lane);
            const float4 k4b = __ldcs(reinterpret_cast<const float4*>(Kc + ((size_t)slotB * H_ + h) * D_) + lane);
            const float4 v4b = __ldcs(reinterpret_cast<const float4*>(Vc + ((size_t)slotB * H_ + h) * D_) + lane);

            float dotA = q4.x * k4a.x + q4.y * k4a.y + q4.z * k4a.z + q4.w * k4a.w;
            float dotB = q4.x * k4b.x + q4.y * k4b.y + q4.z * k4b.z + q4.w * k4b.w;
            #pragma unroll
            for (int o = 16; o; o >>= 1) {
                dotA += __shfl_xor_sync(0xffffffffu, dotA, o);
                dotB += __shfl_xor_sync(0xffffffffu, dotB, o);
            }
            const float scA = dotA * scale + sh_mask[sA - s0];
            const float scB = dotB * scale + sh_mask[sB - s0];

            const float mn   = fmaxf(m, fmaxf(scA, scB));
            const float corr = __expf(m - mn);
            const float pA   = __expf(scA - mn);
            const float pB   = __expf(scB - mn);
            l = l * corr + pA + pB;
            acc.x = acc.x * corr + pA * v4a.x + pB * v4b.x;
            acc.y = acc.y * corr + pA * v4a.y + pB * v4b.y;
            acc.z = acc.z * corr + pA * v4a.z + pB * v4b.z;
            acc.w = acc.w * corr + pA * v4a.w + pB * v4b.w;
            m = mn;
        }
        if (s < send) {
            const int slot = sh_fs[(s >> 4) - f0] * 16 + (s & 15);
            const float4 k4 = __ldcs(reinterpret_cast<const float4*>(Kc + ((size_t)slot * H_ + h) * D_) + lane);
            const float4 v4 = __ldcs(reinterpret_cast<const float4*>(Vc + ((size_t)slot * H_ + h) * D_) + lane);
            float dot = q4.x * k4.x + q4.y * k4.y + q4.z * k4.z + q4.w * k4.w;
            #pragma unroll
            for (int o = 16; o; o >>= 1) dot += __shfl_xor_sync(0xffffffffu, dot, o);
            const float sc = dot * scale + sh_mask[s - s0];
            const float mn   = fmaxf(m, sc);
            const float corr = __expf(m - mn);
            const float p    = __expf(sc - mn);
            l = l * corr + p;
            acc.x = acc.x * corr + p * v4.x;
            acc.y = acc.y * corr + p * v4.y;
            acc.z = acc.z * corr + p * v4.z;
            acc.w = acc.w * corr + p * v4.w;
            m = mn;
        }

        // New token (position == cache_length[b]): warp 0 of the owning split.
        if (w == 0 && newpos >= s0 && newpos < s1) {
            const float4 k4 = reinterpret_cast<const float4*>(sh_k)[lane];
            const float4 v4 = reinterpret_cast<const float4*>(sh_v)[lane];
            float dot = q4.x * k4.x + q4.y * k4.y + q4.z * k4.z + q4.w * k4.w;
            #pragma unroll
            for (int o = 16; o; o >>= 1) dot += __shfl_xor_sync(0xffffffffu, dot, o);
            const float sc = dot * scale + sh_mask[newpos - s0];
            const float mn   = fmaxf(m, sc);
            const float corr = __expf(m - mn);
            const float p    = __expf(sc - mn);
            l = l * corr + p;
            acc.x = acc.x * corr + p * v4.x;
            acc.y = acc.y * corr + p * v4.y;
            acc.z = acc.z * corr + p * v4.z;
            acc.w = acc.w * corr + p * v4.w;
            m = mn;
        }

        // Merge 8 warps in shared, write this split's partial.
        if (lane == 0) { sh_m[w] = m; sh_l[w] = l; }
        reinterpret_cast<float4*>(sh_acc[w])[lane] = acc;
        __syncthreads();

        if (tid < D_) {
            float M = sh_m[0];
            #pragma unroll
            for (int i = 1; i < NWARP; i++) M = fmaxf(M, sh_m[i]);
            float od = 0.f, lt = 0.f;
            #pragma unroll
            for (int i = 0; i < NWARP; i++) {
                const float e = __expf(sh_m[i] - M);
                od += e * sh_acc[i][tid];
                lt += e * sh_l[i];
            }
            g_po[(pbase + split) * D_ + tid] = od;
            if (tid == 0) { g_pm[pbase + split] = M; g_pl[pbase + split] = lt; }
        }
        __threadfence();
    }

    // Arrival + last-CTA combine.
    if (tid == 0) sh_rank = atomicAdd(&g_cnt[bh], 1u);
    __syncthreads();

    if (sh_rank == NSPLIT - 1) {
        if (tid < D_) {
            float M = -1e30f;
            for (int i = 0; i < nact; i++) M = fmaxf(M, g_pm[pbase + i]);
            float denom = 0.f, od = 0.f;
            for (int i = 0; i < nact; i++) {
                const float e = __expf(g_pm[pbase + i] - M);
                denom += e * g_pl[pbase + i];
                od    += e * g_po[(pbase + i) * D_ + tid];
            }
            out[(size_t)bh * D_ + tid] = od / denom;
        }
        if (tid == 0) g_cnt[bh] = 0;   // reset for next graph replay
    }
}

// Inputs (metadata order):
//  0 Q  1 K  2 V  3 Kcache  4 Vcache  5 cos  6 sin  7 mask
//  8 input_length  9 cache_length  10 save_slots  11 fetch_slots  12 max_s
extern "C" void kernel_launch(void* const* d_in, const int* in_sizes, int n_in,
                              void* d_out, int out_size)
{
    const float* Q    = (const float*)d_in[0];
    const float* K    = (const float*)d_in[1];
    const float* V    = (const float*)d_in[2];
    const float* Kc   = (const float*)d_in[3];
    const float* Vc   = (const float*)d_in[4];
    const float* cosT = (const float*)d_in[5];
    const float* sinT = (const float*)d_in[6];
    const float* mask = (const float*)d_in[7];
    const int*   clen = (const int*)d_in[9];
    const int*   fsl  = (const int*)d_in[11];
    float* out = (float*)d_out;

    dim3 grid(NSPLIT, H_, B_);
    paged_attn_fused<<<grid, NTHREAD>>>(Q, K, V, Kc, Vc, cosT, sinT, mask, clen, fsl, out);
}